// round 3
// baseline (speedup 1.0000x reference)
#include <cuda_runtime.h>
#include <math_constants.h>
#include <cstdint>

#define Bn 4
#define Tn 2048
#define Cn 1024
#define Hn 16
#define Dn 64
#define BT (Bn*Tn)      // 8192
#define NTILES (Tn/64)  // 32

// Scratch (device globals — no allocation allowed)
__device__ float g_q[Bn*Hn*Tn*Dn];   // [bh, t, d]
__device__ float g_k[Bn*Hn*Tn*Dn];
__device__ float g_v[Bn*Hn*Tn*Dn];
__device__ float g_y[BT*Cn];         // [b*T+t, C]  (attention output, pre-proj)

// ===========================================================================
// mma.sync tf32 GEMM with 2-term tf32 split (3 MMAs): out = A[M,K]@W[K,N]+bias
// M=8192, N=K=1024. CTA: 128x128, BK=16, 8 warps (4m x 2n), warp tile 32x64.
// Fragments are pre-shuffled into per-lane layout in SMEM at store time.
// ===========================================================================

__device__ __forceinline__ uint32_t to_tf32(float a) {
    uint32_t r;
    asm("cvt.rna.tf32.f32 %0, %1;" : "=r"(r) : "f"(a));
    return r;
}

__device__ __forceinline__ void cvt_hilo(float a, uint32_t& hi, uint32_t& lo) {
    hi = to_tf32(a);
    lo = to_tf32(a - __uint_as_float(hi));
}

__device__ __forceinline__ void mma_tf32(float d[4], const uint32_t a[4], const uint32_t b[2]) {
    asm volatile(
        "mma.sync.aligned.m16n8k8.row.col.f32.tf32.tf32.f32 "
        "{%0,%1,%2,%3}, {%4,%5,%6,%7}, {%8,%9}, {%0,%1,%2,%3};"
        : "+f"(d[0]), "+f"(d[1]), "+f"(d[2]), "+f"(d[3])
        : "r"(a[0]), "r"(a[1]), "r"(a[2]), "r"(a[3]), "r"(b[0]), "r"(b[1]));
}

// SMEM (uint32 units) per stage:
//   Ah [2 k8][8 m16][32 lane][4 reg]  : 2048
//   Al                                 : 2048
//   Bh [2 k8][16 n8][32 lane][2 reg]  : 2048
//   Bl                                 : 2048
#define STG_U32 8192
#define GEMM_SMEM (2 * STG_U32 * 4)   // 65536 bytes

__device__ __forceinline__ int aoff(int k8, int m16, int lane, int reg) {
    return ((k8 * 8 + m16) * 32 + lane) * 4 + reg;
}
__device__ __forceinline__ int boff(int k8, int n8, int lane, int reg) {
    return 4096 + ((k8 * 16 + n8) * 32 + lane) * 2 + reg;
}

template<bool REMAP>
__device__ __forceinline__ void gemm_mma_body(
    const float* __restrict__ A, const float* __restrict__ W,
    const float* __restrict__ bias, float* __restrict__ out)
{
    extern __shared__ uint32_t sm_u[];

    const int tid  = threadIdx.x;
    const int wid  = tid >> 5;
    const int lane = tid & 31;
    const int bm = blockIdx.y, bn = blockIdx.x;
    const int warp_m = wid & 3;      // 0..3 (32 rows each)
    const int warp_n = wid >> 2;     // 0..1 (64 cols each)

    // ---- loader index precompute ----
    // A tile: 128m x 16k.  idx = tid + 256*i -> m = idx>>2, quad = idx&3 (k=4*quad)
    const int aM0   = tid >> 2;
    const int aQ    = tid & 3;
    // B tile: 16k x 128n.  idx = tid + 256*i -> k = idx>>5, nq = idx&31 (n=4*nq)
    const int bK0   = tid >> 5;
    const int bN0   = (tid & 31) << 2;

    const float* Abase = A + (size_t)(bm * 128) * 1024;
    const float* Wbase = W + (size_t)(bn * 128);

    float d[2][8][4];
    #pragma unroll
    for (int t = 0; t < 2; t++)
        #pragma unroll
        for (int u = 0; u < 8; u++)
            #pragma unroll
            for (int v = 0; v < 4; v++) d[t][u][v] = 0.f;

    float4 rA[2], rB[2];

    // prologue: LDG chunk 0
    {
        #pragma unroll
        for (int i = 0; i < 2; i++) {
            const int m = aM0 + 64 * i;
            rA[i] = *(const float4*)(Abase + (size_t)m * 1024 + 4 * aQ);
            const int k = bK0 + 8 * i;
            rB[i] = *(const float4*)(Wbase + (size_t)k * 1024 + bN0);
        }
    }

    for (int kc = 0; kc < 64; kc++) {
        uint32_t* st = sm_u + (kc & 1) * STG_U32;

        // ---- convert + STS into fragment layout ----
        #pragma unroll
        for (int i = 0; i < 2; i++) {
            // A: element (m, 4*aQ + e)
            const int m = aM0 + 64 * i;
            const int k8   = aQ >> 1;
            const int regA = ((aQ & 1) << 1) + ((m >> 3) & 1);
            const int m16  = m >> 4;
            const int lbase = (m & 7) << 2;
            uint32_t h, l;
            cvt_hilo(rA[i].x, h, l);
            st[aoff(k8, m16, lbase + 0, regA)] = h;
            st[2048 + aoff(k8, m16, lbase + 0, regA)] = l;
            cvt_hilo(rA[i].y, h, l);
            st[aoff(k8, m16, lbase + 1, regA)] = h;
            st[2048 + aoff(k8, m16, lbase + 1, regA)] = l;
            cvt_hilo(rA[i].z, h, l);
            st[aoff(k8, m16, lbase + 2, regA)] = h;
            st[2048 + aoff(k8, m16, lbase + 2, regA)] = l;
            cvt_hilo(rA[i].w, h, l);
            st[aoff(k8, m16, lbase + 3, regA)] = h;
            st[2048 + aoff(k8, m16, lbase + 3, regA)] = l;

            // B: element (k, bN0 + e)
            const int k = bK0 + 8 * i;
            const int bk8  = k >> 3;
            const int regB = ((k & 7) >= 4) ? 1 : 0;
            const int kq   = k & 3;
            const float be[4] = {rB[i].x, rB[i].y, rB[i].z, rB[i].w};
            #pragma unroll
            for (int e = 0; e < 4; e++) {
                const int n = bN0 + e;
                const int n8 = n >> 3;
                const int ln = ((n & 7) << 2) + kq;
                uint32_t bh, bl;
                cvt_hilo(be[e], bh, bl);
                st[boff(bk8, n8, ln, regB)] = bh;
                st[2048 + boff(bk8, n8, ln, regB)] = bl;
            }
        }
        __syncthreads();

        // ---- prefetch next chunk ----
        if (kc < 63) {
            const float* An = Abase + (kc + 1) * 16;
            const float* Wn = Wbase + (size_t)((kc + 1) * 16) * 1024;
            #pragma unroll
            for (int i = 0; i < 2; i++) {
                const int m = aM0 + 64 * i;
                rA[i] = *(const float4*)(An + (size_t)m * 1024 + 4 * aQ);
                const int k = bK0 + 8 * i;
                rB[i] = *(const float4*)(Wn + (size_t)k * 1024 + bN0);
            }
        }

        // ---- consume: 2 k8 steps ----
        #pragma unroll
        for (int k8 = 0; k8 < 2; k8++) {
            uint32_t Ah[2][4], Al[2][4];
            #pragma unroll
            for (int t = 0; t < 2; t++) {
                const int m16 = warp_m * 2 + t;
                *(uint4*)Ah[t] = *(const uint4*)&st[aoff(k8, m16, lane, 0)];
                *(uint4*)Al[t] = *(const uint4*)&st[2048 + aoff(k8, m16, lane, 0)];
            }
            uint32_t Bh[8][2], Bl[8][2];
            #pragma unroll
            for (int u = 0; u < 8; u++) {
                const int n8 = warp_n * 8 + u;
                *(uint2*)Bh[u] = *(const uint2*)&st[boff(k8, n8, lane, 0)];
                *(uint2*)Bl[u] = *(const uint2*)&st[2048 + boff(k8, n8, lane, 0)];
            }
            #pragma unroll
            for (int t = 0; t < 2; t++)
                #pragma unroll
                for (int u = 0; u < 8; u++) {
                    mma_tf32(d[t][u], Ah[t], Bh[u]);
                    mma_tf32(d[t][u], Ah[t], Bl[u]);
                    mma_tf32(d[t][u], Al[t], Bh[u]);
                }
        }
        __syncthreads();
    }

    // ---- epilogue ----
    #pragma unroll
    for (int t = 0; t < 2; t++) {
        const int rowA = bm * 128 + warp_m * 32 + t * 16 + (lane >> 2);
        #pragma unroll
        for (int half = 0; half < 2; half++) {
            const int m = rowA + half * 8;
            #pragma unroll
            for (int u = 0; u < 8; u++) {
                const int col = bn * 128 + warp_n * 64 + u * 8 + ((lane & 3) << 1);
                float2 o;
                o.x = d[t][u][half * 2 + 0] + __ldg(&bias[col]);
                o.y = d[t][u][half * 2 + 1] + __ldg(&bias[col + 1]);
                if (REMAP) {
                    const int b = m >> 11, tt = m & 2047;
                    const int h = col >> 6, d0 = col & 63;
                    *(float2*)(out + (((size_t)(b * Hn + h) * Tn) + tt) * Dn + d0) = o;
                } else {
                    *(float2*)(out + (size_t)m * 1024 + col) = o;
                }
            }
        }
    }
}

__global__ __launch_bounds__(256) void gemm_qkv_tc(
    const float* __restrict__ X,
    const float* __restrict__ Wq, const float* __restrict__ bq,
    const float* __restrict__ Wk, const float* __restrict__ bk,
    const float* __restrict__ Wv, const float* __restrict__ bv)
{
    const float* W; const float* bias; float* out;
    if (blockIdx.z == 0)      { W = Wq; bias = bq; out = g_q; }
    else if (blockIdx.z == 1) { W = Wk; bias = bk; out = g_k; }
    else                      { W = Wv; bias = bv; out = g_v; }
    gemm_mma_body<true>(X, W, bias, out);
}

__global__ __launch_bounds__(256) void gemm_proj_tc(
    const float* __restrict__ Wp, const float* __restrict__ bp,
    float* __restrict__ out)
{
    gemm_mma_body<false>(g_y, Wp, bp, out);
}

// ---------------------------------------------------------------------------
// Attention kernel: one CTA per (bh, 64-query tile). 256 threads. (unchanged)
// ---------------------------------------------------------------------------
#define SST 66

__device__ __forceinline__ void load_tile_T(float* dst, const float* __restrict__ src, int tid)
{
    const int row = tid >> 4;
    const int d0 = (tid & 15) << 2;
    #pragma unroll
    for (int it = 0; it < 4; it++) {
        const int r = row + it * 16;
        float4 v4 = *(const float4*)(src + (size_t)r * Dn + d0);
        dst[(d0 + 0) * SST + r] = v4.x;
        dst[(d0 + 1) * SST + r] = v4.y;
        dst[(d0 + 2) * SST + r] = v4.z;
        dst[(d0 + 3) * SST + r] = v4.w;
    }
}

__device__ __forceinline__ void load_tile_N(float* dst, const float* __restrict__ src, int tid)
{
    const int row = tid >> 4;
    const int d0 = (tid & 15) << 2;
    #pragma unroll
    for (int it = 0; it < 4; it++) {
        const int r = row + it * 16;
        float4 v4 = *(const float4*)(src + (size_t)r * Dn + d0);
        float* p = dst + r * SST + d0;
        p[0] = v4.x; p[1] = v4.y; p[2] = v4.z; p[3] = v4.w;
    }
}

__device__ __forceinline__ void compute_scores(
    const float* Qs, const float* Ks, int iBase, int jBase, float s[4][4])
{
    #pragma unroll
    for (int r = 0; r < 4; r++)
        #pragma unroll
        for (int c = 0; c < 4; c++) s[r][c] = 0.f;

    #pragma unroll 16
    for (int kk = 0; kk < 64; kk++) {
        const float* qrow = Qs + kk * SST;
        const float* krow = Ks + kk * SST;
        float2 qa = *(const float2*)(qrow + iBase);
        float2 qb = *(const float2*)(qrow + iBase + 2);
        float2 ka = *(const float2*)(krow + jBase);
        float2 kb = *(const float2*)(krow + jBase + 2);
        float a[4] = {qa.x, qa.y, qb.x, qb.y};
        float b[4] = {ka.x, ka.y, kb.x, kb.y};
        #pragma unroll
        for (int r = 0; r < 4; r++)
            #pragma unroll
            for (int c = 0; c < 4; c++)
                s[r][c] += a[r] * b[c];
    }
}

__global__ __launch_bounds__(256) void attn_kernel(float* __restrict__ att)
{
    extern __shared__ float smf[];
    float* Qs = smf;
    float* Ks = smf + 64 * SST;
    float* Vs = smf + 2 * 64 * SST;
    float* Ps = smf + 3 * 64 * SST;

    const int bh = blockIdx.y;
    const int qt = blockIdx.x;
    const int qbase = qt * 64;
    const int tid = threadIdx.x;
    const int iBase = (tid >> 4) << 2;
    const int cBase = (tid & 15) << 2;

    const float* qp = g_q + ((size_t)bh * Tn + qbase) * Dn;
    const float* kp = g_k + (size_t)bh * Tn * Dn;
    const float* vp = g_v + (size_t)bh * Tn * Dn;
    float* attp = att + ((size_t)bh * Tn + qbase) * Tn;

    load_tile_T(Qs, qp, tid);
    __syncthreads();

    const float scale = 0.125f;

    float m[4], l[4];
    #pragma unroll
    for (int r = 0; r < 4; r++) { m[r] = -CUDART_INF_F; l[r] = 0.f; }

    for (int kt = 0; kt <= qt; kt++) {
        load_tile_T(Ks, kp + (size_t)kt * 64 * Dn, tid);
        __syncthreads();

        float s[4][4];
        compute_scores(Qs, Ks, iBase, cBase, s);

        const bool diag = (kt == qt);
        #pragma unroll
        for (int r = 0; r < 4; r++) {
            #pragma unroll
            for (int c = 0; c < 4; c++) {
                s[r][c] *= scale;
                if (diag) {
                    const int gi = qbase + iBase + r;
                    const int gj = kt * 64 + cBase + c;
                    if (gj > gi) s[r][c] = -CUDART_INF_F;
                }
            }
            float tm = s[r][0];
            #pragma unroll
            for (int c = 1; c < 4; c++) tm = fmaxf(tm, s[r][c]);
            const float mn = fmaxf(m[r], tm);
            if (mn > -CUDART_INF_F) {
                float sum = 0.f;
                #pragma unroll
                for (int c = 0; c < 4; c++) sum += __expf(s[r][c] - mn);
                l[r] = l[r] * __expf(m[r] - mn) + sum;
                m[r] = mn;
            }
        }
        __syncthreads();
    }

    #pragma unroll
    for (int r = 0; r < 4; r++) {
        #pragma unroll
        for (int off = 8; off > 0; off >>= 1) {
            const float om = __shfl_xor_sync(0xffffffffu, m[r], off);
            const float ol = __shfl_xor_sync(0xffffffffu, l[r], off);
            const float mn = fmaxf(m[r], om);
            if (mn > -CUDART_INF_F) {
                l[r] = l[r] * __expf(m[r] - mn) + ol * __expf(om - mn);
                m[r] = mn;
            }
        }
    }
    float invl[4];
    #pragma unroll
    for (int r = 0; r < 4; r++) invl[r] = 1.f / l[r];

    float yacc[4][4];
    #pragma unroll
    for (int r = 0; r < 4; r++)
        #pragma unroll
        for (int c = 0; c < 4; c++) yacc[r][c] = 0.f;

    for (int kt = 0; kt < NTILES; kt++) {
        if (kt <= qt) {
            __syncthreads();
            load_tile_T(Ks, kp + (size_t)kt * 64 * Dn, tid);
            load_tile_N(Vs, vp + (size_t)kt * 64 * Dn, tid);
            __syncthreads();

            float s[4][4];
            compute_scores(Qs, Ks, iBase, cBase, s);

            const bool diag = (kt == qt);
            float p[4][4];
            #pragma unroll
            for (int r = 0; r < 4; r++) {
                #pragma unroll
                for (int c = 0; c < 4; c++) {
                    bool valid = true;
                    if (diag) {
                        const int gi = qbase + iBase + r;
                        const int gj = kt * 64 + cBase + c;
                        valid = (gj <= gi);
                    }
                    p[r][c] = valid ? __expf(s[r][c] * scale - m[r]) * invl[r] : 0.f;
                }
                float4 pv = make_float4(p[r][0], p[r][1], p[r][2], p[r][3]);
                *(float4*)(attp + (size_t)(iBase + r) * Tn + kt * 64 + cBase) = pv;
                #pragma unroll
                for (int c = 0; c < 4; c++)
                    Ps[(cBase + c) * SST + iBase + r] = p[r][c];
            }
            __syncthreads();

            #pragma unroll 16
            for (int j = 0; j < 64; j++) {
                const float* prow = Ps + j * SST;
                const float* vrow = Vs + j * SST;
                float2 pa = *(const float2*)(prow + iBase);
                float2 pb = *(const float2*)(prow + iBase + 2);
                float2 va = *(const float2*)(vrow + cBase);
                float2 vb = *(const float2*)(vrow + cBase + 2);
                float pr[4] = {pa.x, pa.y, pb.x, pb.y};
                float vv[4] = {va.x, va.y, vb.x, vb.y};
                #pragma unroll
                for (int r = 0; r < 4; r++)
                    #pragma unroll
                    for (int c = 0; c < 4; c++)
                        yacc[r][c] += pr[r] * vv[c];
            }
        } else {
            const float4 z = make_float4(0.f, 0.f, 0.f, 0.f);
            #pragma unroll
            for (int r = 0; r < 4; r++)
                *(float4*)(attp + (size_t)(iBase + r) * Tn + kt * 64 + cBase) = z;
        }
    }

    const int b = bh >> 4, h = bh & 15;
    #pragma unroll
    for (int r = 0; r < 4; r++) {
        const int t = qbase + iBase + r;
        float4 yv = make_float4(yacc[r][0], yacc[r][1], yacc[r][2], yacc[r][3]);
        *(float4*)(g_y + ((size_t)(b * Tn + t)) * Cn + h * Dn + cBase) = yv;
    }
}

// ---------------------------------------------------------------------------
extern "C" void kernel_launch(void* const* d_in, const int* in_sizes, int n_in,
                              void* d_out, int out_size)
{
    const float* x  = (const float*)d_in[0];
    const float* Wq = (const float*)d_in[1];
    const float* bq = (const float*)d_in[2];
    const float* Wk = (const float*)d_in[3];
    const float* bk = (const float*)d_in[4];
    const float* Wv = (const float*)d_in[5];
    const float* bv = (const float*)d_in[6];
    const float* Wp = (const float*)d_in[7];
    const float* bp = (const float*)d_in[8];

    float* y_out   = (float*)d_out;                       // [B,T,C]
    float* att_out = y_out + (size_t)BT * Cn;             // [B,H,T,T]

    cudaFuncSetAttribute(gemm_qkv_tc,  cudaFuncAttributeMaxDynamicSharedMemorySize, GEMM_SMEM);
    cudaFuncSetAttribute(gemm_proj_tc, cudaFuncAttributeMaxDynamicSharedMemorySize, GEMM_SMEM);

    // QKV projections on tensor cores (mma.sync tf32 split)
    gemm_qkv_tc<<<dim3(8, 64, 3), 256, GEMM_SMEM>>>(x, Wq, bq, Wk, bk, Wv, bv);

    // Fused attention (scores -> softmax -> att write -> att@V)
    const int smem = 4 * 64 * SST * (int)sizeof(float);   // 67584 B
    cudaFuncSetAttribute(attn_kernel, cudaFuncAttributeMaxDynamicSharedMemorySize, smem);
    attn_kernel<<<dim3(NTILES, Bn * Hn), 256, smem>>>(att_out);

    // Output projection on tensor cores
    gemm_proj_tc<<<dim3(8, 64), 256, GEMM_SMEM>>>(Wp, bp, y_out);
}

// round 4
// speedup vs baseline: 1.9863x; 1.9863x over previous
#include <cuda_runtime.h>
#include <cuda_bf16.h>
#include <math_constants.h>
#include <cstdint>

#define Bn 4
#define Tn 2048
#define Cn 1024
#define Hn 16
#define Dn 64
#define BT (Bn*Tn)      // 8192
#define NTILES (Tn/64)  // 32

// Scratch (device globals — no allocation allowed)
__device__ float g_q[Bn*Hn*Tn*Dn];   // [bh, t, d]
__device__ float g_k[Bn*Hn*Tn*Dn];
__device__ float g_v[Bn*Hn*Tn*Dn];
__device__ float g_y[BT*Cn];         // [b*T+t, C]  (attention output, pre-proj)

// ===========================================================================
// bf16-split mma.sync GEMM: out = A[M,K]@W[K,N]+bias  (M=8192, N=K=1024)
// a = ah + al (bf16 each); D += Ah*Bh + Ah*Bl + Al*Bh  (al*bl dropped, ~2^-16)
// CTA 128x128, BK=32, 8 warps (4m x 2n), warp tile 32x64, m16n8k16 MMAs.
// SMEM: A[m][k] rows padded to 80B; B[k][n] rows padded to 272B; ldmatrix.
// ===========================================================================

#define APITCH 80
#define BPITCH 272
#define AL_OFF 10240     // 128*80
#define BH_OFF 20480
#define BL_OFF 29184     // BH_OFF + 32*272
#define STAGE_B 37888    // BL_OFF + 32*272
#define GEMM_SMEM (2*STAGE_B)   // 75776

__device__ __forceinline__ uint32_t smem_u32(const void* p) {
    uint32_t a;
    asm("{ .reg .u64 t; cvta.to.shared.u64 t, %1; cvt.u32.u64 %0, t; }"
        : "=r"(a) : "l"(p));
    return a;
}

__device__ __forceinline__ void split2(float f0, float f1, uint32_t& hi, uint32_t& lo) {
    __nv_bfloat16 h0 = __float2bfloat16(f0);
    __nv_bfloat16 h1 = __float2bfloat16(f1);
    __nv_bfloat16 l0 = __float2bfloat16(f0 - __bfloat162float(h0));
    __nv_bfloat16 l1 = __float2bfloat16(f1 - __bfloat162float(h1));
    hi = (uint32_t)__bfloat16_as_ushort(h0) | ((uint32_t)__bfloat16_as_ushort(h1) << 16);
    lo = (uint32_t)__bfloat16_as_ushort(l0) | ((uint32_t)__bfloat16_as_ushort(l1) << 16);
}

__device__ __forceinline__ void ldm_x4(uint32_t r[4], uint32_t addr) {
    asm volatile("ldmatrix.sync.aligned.m8n8.x4.shared.b16 {%0,%1,%2,%3}, [%4];"
        : "=r"(r[0]), "=r"(r[1]), "=r"(r[2]), "=r"(r[3]) : "r"(addr));
}

__device__ __forceinline__ void ldm_x4_t(uint32_t r[4], uint32_t addr) {
    asm volatile("ldmatrix.sync.aligned.m8n8.x4.trans.shared.b16 {%0,%1,%2,%3}, [%4];"
        : "=r"(r[0]), "=r"(r[1]), "=r"(r[2]), "=r"(r[3]) : "r"(addr));
}

__device__ __forceinline__ void mma_bf16(float d[4], const uint32_t a[4], const uint32_t b[2]) {
    asm volatile(
        "mma.sync.aligned.m16n8k16.row.col.f32.bf16.bf16.f32 "
        "{%0,%1,%2,%3}, {%4,%5,%6,%7}, {%8,%9}, {%0,%1,%2,%3};"
        : "+f"(d[0]), "+f"(d[1]), "+f"(d[2]), "+f"(d[3])
        : "r"(a[0]), "r"(a[1]), "r"(a[2]), "r"(a[3]), "r"(b[0]), "r"(b[1]));
}

template<bool REMAP>
__device__ __forceinline__ void gemm_mma_body(
    const float* __restrict__ A, const float* __restrict__ W,
    const float* __restrict__ bias, float* __restrict__ out)
{
    extern __shared__ char smc[];

    const int tid  = threadIdx.x;
    const int wid  = tid >> 5;
    const int lane = tid & 31;
    const int bm = blockIdx.y, bn = blockIdx.x;
    const int warp_m = wid & 3;      // 32 rows
    const int warp_n = wid >> 2;     // 64 cols

    // loaders
    const int aM0 = tid >> 3;        // + 32*i
    const int aQ  = tid & 7;         // k quad (4 floats)
    const int bK0 = tid >> 5;        // + 8*i
    const int bNq = tid & 31;        // n quad

    const float* Abase = A + (size_t)(bm * 128) * 1024;
    const float* Wbase = W + (size_t)(bn * 128);

    // consumer address bases (lane-dependent)
    const uint32_t sb = smem_u32(smc);
    const int l15 = lane & 15;
    const int lhi = lane >> 4;
    const uint32_t aBase = sb + (uint32_t)((warp_m * 32 + l15) * APITCH + lhi * 16);
    const uint32_t bBase = sb + BH_OFF + (uint32_t)(l15 * BPITCH + warp_n * 128 + lhi * 16);

    float d[2][8][4];
    #pragma unroll
    for (int t = 0; t < 2; t++)
        #pragma unroll
        for (int u = 0; u < 8; u++)
            #pragma unroll
            for (int v = 0; v < 4; v++) d[t][u][v] = 0.f;

    float4 rA[4], rB[4];

    // prologue: LDG chunk 0
    #pragma unroll
    for (int i = 0; i < 4; i++) {
        rA[i] = *(const float4*)(Abase + (size_t)(aM0 + 32 * i) * 1024 + 4 * aQ);
        rB[i] = *(const float4*)(Wbase + (size_t)(bK0 + 8 * i) * 1024 + 4 * bNq);
    }

    for (int kc = 0; kc < 32; kc++) {
        const int stg = kc & 1;
        char* s = smc + stg * STAGE_B;
        const uint32_t stgOff = stg * STAGE_B;

        // ---- STS current chunk (convert to bf16 hi/lo) ----
        #pragma unroll
        for (int i = 0; i < 4; i++) {
            const int m = aM0 + 32 * i;
            uint32_t h0, l0, h1, l1;
            split2(rA[i].x, rA[i].y, h0, l0);
            split2(rA[i].z, rA[i].w, h1, l1);
            *(uint2*)(s + m * APITCH + aQ * 8)          = make_uint2(h0, h1);
            *(uint2*)(s + AL_OFF + m * APITCH + aQ * 8) = make_uint2(l0, l1);

            const int k = bK0 + 8 * i;
            split2(rB[i].x, rB[i].y, h0, l0);
            split2(rB[i].z, rB[i].w, h1, l1);
            *(uint2*)(s + BH_OFF + k * BPITCH + bNq * 8) = make_uint2(h0, h1);
            *(uint2*)(s + BL_OFF + k * BPITCH + bNq * 8) = make_uint2(l0, l1);
        }
        __syncthreads();

        // ---- prefetch next chunk ----
        if (kc < 31) {
            const float* An = Abase + (kc + 1) * 32;
            const float* Wn = Wbase + (size_t)((kc + 1) * 32) * 1024;
            #pragma unroll
            for (int i = 0; i < 4; i++) {
                rA[i] = *(const float4*)(An + (size_t)(aM0 + 32 * i) * 1024 + 4 * aQ);
                rB[i] = *(const float4*)(Wn + (size_t)(bK0 + 8 * i) * 1024 + 4 * bNq);
            }
        }

        // ---- consume: 2 k16 steps ----
        #pragma unroll
        for (int ss = 0; ss < 2; ss++) {
            uint32_t Ah[2][4], Al_[2][4];
            #pragma unroll
            for (int t = 0; t < 2; t++) {
                const uint32_t aa = aBase + stgOff + (uint32_t)(t * 16 * APITCH + ss * 32);
                ldm_x4(Ah[t], aa);
                ldm_x4(Al_[t], aa + AL_OFF);
            }
            #pragma unroll
            for (int half = 0; half < 2; half++) {
                uint32_t Bh[4][2], Bl[4][2];
                #pragma unroll
                for (int gp = 0; gp < 2; gp++) {
                    const int g2 = half * 2 + gp;
                    const uint32_t ba = bBase + stgOff + (uint32_t)(ss * 16 * BPITCH + g2 * 32);
                    uint32_t r[4];
                    ldm_x4_t(r, ba);
                    Bh[gp*2][0] = r[0]; Bh[gp*2][1] = r[1];
                    Bh[gp*2+1][0] = r[2]; Bh[gp*2+1][1] = r[3];
                    ldm_x4_t(r, ba + (BL_OFF - BH_OFF));
                    Bl[gp*2][0] = r[0]; Bl[gp*2][1] = r[1];
                    Bl[gp*2+1][0] = r[2]; Bl[gp*2+1][1] = r[3];
                }
                #pragma unroll
                for (int t = 0; t < 2; t++)
                    #pragma unroll
                    for (int u = 0; u < 4; u++) {
                        const int un = half * 4 + u;
                        mma_bf16(d[t][un], Ah[t], Bh[u]);
                        mma_bf16(d[t][un], Ah[t], Bl[u]);
                        mma_bf16(d[t][un], Al_[t], Bh[u]);
                    }
            }
        }
    }

    // ---- epilogue ----
    #pragma unroll
    for (int t = 0; t < 2; t++) {
        const int rowA = bm * 128 + warp_m * 32 + t * 16 + (lane >> 2);
        #pragma unroll
        for (int half = 0; half < 2; half++) {
            const int m = rowA + half * 8;
            #pragma unroll
            for (int u = 0; u < 8; u++) {
                const int col = bn * 128 + warp_n * 64 + u * 8 + ((lane & 3) << 1);
                float2 o;
                o.x = d[t][u][half * 2 + 0] + __ldg(&bias[col]);
                o.y = d[t][u][half * 2 + 1] + __ldg(&bias[col + 1]);
                if (REMAP) {
                    const int b = m >> 11, tt = m & 2047;
                    const int h = col >> 6, d0 = col & 63;
                    *(float2*)(out + (((size_t)(b * Hn + h) * Tn) + tt) * Dn + d0) = o;
                } else {
                    *(float2*)(out + (size_t)m * 1024 + col) = o;
                }
            }
        }
    }
}

__global__ __launch_bounds__(256) void gemm_qkv_tc(
    const float* __restrict__ X,
    const float* __restrict__ Wq, const float* __restrict__ bq,
    const float* __restrict__ Wk, const float* __restrict__ bk,
    const float* __restrict__ Wv, const float* __restrict__ bv)
{
    const float* W; const float* bias; float* out;
    if (blockIdx.z == 0)      { W = Wq; bias = bq; out = g_q; }
    else if (blockIdx.z == 1) { W = Wk; bias = bk; out = g_k; }
    else                      { W = Wv; bias = bv; out = g_v; }
    gemm_mma_body<true>(X, W, bias, out);
}

__global__ __launch_bounds__(256) void gemm_proj_tc(
    const float* __restrict__ Wp, const float* __restrict__ bp,
    float* __restrict__ out)
{
    gemm_mma_body<false>(g_y, Wp, bp, out);
}

// ---------------------------------------------------------------------------
// Attention kernel: one CTA per (bh, 64-query tile). 256 threads. (unchanged)
// ---------------------------------------------------------------------------
#define SST 66

__device__ __forceinline__ void load_tile_T(float* dst, const float* __restrict__ src, int tid)
{
    const int row = tid >> 4;
    const int d0 = (tid & 15) << 2;
    #pragma unroll
    for (int it = 0; it < 4; it++) {
        const int r = row + it * 16;
        float4 v4 = *(const float4*)(src + (size_t)r * Dn + d0);
        dst[(d0 + 0) * SST + r] = v4.x;
        dst[(d0 + 1) * SST + r] = v4.y;
        dst[(d0 + 2) * SST + r] = v4.z;
        dst[(d0 + 3) * SST + r] = v4.w;
    }
}

__device__ __forceinline__ void load_tile_N(float* dst, const float* __restrict__ src, int tid)
{
    const int row = tid >> 4;
    const int d0 = (tid & 15) << 2;
    #pragma unroll
    for (int it = 0; it < 4; it++) {
        const int r = row + it * 16;
        float4 v4 = *(const float4*)(src + (size_t)r * Dn + d0);
        float* p = dst + r * SST + d0;
        p[0] = v4.x; p[1] = v4.y; p[2] = v4.z; p[3] = v4.w;
    }
}

__device__ __forceinline__ void compute_scores(
    const float* Qs, const float* Ks, int iBase, int jBase, float s[4][4])
{
    #pragma unroll
    for (int r = 0; r < 4; r++)
        #pragma unroll
        for (int c = 0; c < 4; c++) s[r][c] = 0.f;

    #pragma unroll 16
    for (int kk = 0; kk < 64; kk++) {
        const float* qrow = Qs + kk * SST;
        const float* krow = Ks + kk * SST;
        float2 qa = *(const float2*)(qrow + iBase);
        float2 qb = *(const float2*)(qrow + iBase + 2);
        float2 ka = *(const float2*)(krow + jBase);
        float2 kb = *(const float2*)(krow + jBase + 2);
        float a[4] = {qa.x, qa.y, qb.x, qb.y};
        float b[4] = {ka.x, ka.y, kb.x, kb.y};
        #pragma unroll
        for (int r = 0; r < 4; r++)
            #pragma unroll
            for (int c = 0; c < 4; c++)
                s[r][c] += a[r] * b[c];
    }
}

__global__ __launch_bounds__(256) void attn_kernel(float* __restrict__ att)
{
    extern __shared__ float smf[];
    float* Qs = smf;
    float* Ks = smf + 64 * SST;
    float* Vs = smf + 2 * 64 * SST;
    float* Ps = smf + 3 * 64 * SST;

    const int bh = blockIdx.y;
    const int qt = blockIdx.x;
    const int qbase = qt * 64;
    const int tid = threadIdx.x;
    const int iBase = (tid >> 4) << 2;
    const int cBase = (tid & 15) << 2;

    const float* qp = g_q + ((size_t)bh * Tn + qbase) * Dn;
    const float* kp = g_k + (size_t)bh * Tn * Dn;
    const float* vp = g_v + (size_t)bh * Tn * Dn;
    float* attp = att + ((size_t)bh * Tn + qbase) * Tn;

    load_tile_T(Qs, qp, tid);
    __syncthreads();

    const float scale = 0.125f;

    float m[4], l[4];
    #pragma unroll
    for (int r = 0; r < 4; r++) { m[r] = -CUDART_INF_F; l[r] = 0.f; }

    for (int kt = 0; kt <= qt; kt++) {
        load_tile_T(Ks, kp + (size_t)kt * 64 * Dn, tid);
        __syncthreads();

        float s[4][4];
        compute_scores(Qs, Ks, iBase, cBase, s);

        const bool diag = (kt == qt);
        #pragma unroll
        for (int r = 0; r < 4; r++) {
            #pragma unroll
            for (int c = 0; c < 4; c++) {
                s[r][c] *= scale;
                if (diag) {
                    const int gi = qbase + iBase + r;
                    const int gj = kt * 64 + cBase + c;
                    if (gj > gi) s[r][c] = -CUDART_INF_F;
                }
            }
            float tm = s[r][0];
            #pragma unroll
            for (int c = 1; c < 4; c++) tm = fmaxf(tm, s[r][c]);
            const float mn = fmaxf(m[r], tm);
            if (mn > -CUDART_INF_F) {
                float sum = 0.f;
                #pragma unroll
                for (int c = 0; c < 4; c++) sum += __expf(s[r][c] - mn);
                l[r] = l[r] * __expf(m[r] - mn) + sum;
                m[r] = mn;
            }
        }
        __syncthreads();
    }

    #pragma unroll
    for (int r = 0; r < 4; r++) {
        #pragma unroll
        for (int off = 8; off > 0; off >>= 1) {
            const float om = __shfl_xor_sync(0xffffffffu, m[r], off);
            const float ol = __shfl_xor_sync(0xffffffffu, l[r], off);
            const float mn = fmaxf(m[r], om);
            if (mn > -CUDART_INF_F) {
                l[r] = l[r] * __expf(m[r] - mn) + ol * __expf(om - mn);
                m[r] = mn;
            }
        }
    }
    float invl[4];
    #pragma unroll
    for (int r = 0; r < 4; r++) invl[r] = 1.f / l[r];

    float yacc[4][4];
    #pragma unroll
    for (int r = 0; r < 4; r++)
        #pragma unroll
        for (int c = 0; c < 4; c++) yacc[r][c] = 0.f;

    for (int kt = 0; kt < NTILES; kt++) {
        if (kt <= qt) {
            __syncthreads();
            load_tile_T(Ks, kp + (size_t)kt * 64 * Dn, tid);
            load_tile_N(Vs, vp + (size_t)kt * 64 * Dn, tid);
            __syncthreads();

            float s[4][4];
            compute_scores(Qs, Ks, iBase, cBase, s);

            const bool diag = (kt == qt);
            float p[4][4];
            #pragma unroll
            for (int r = 0; r < 4; r++) {
                #pragma unroll
                for (int c = 0; c < 4; c++) {
                    bool valid = true;
                    if (diag) {
                        const int gi = qbase + iBase + r;
                        const int gj = kt * 64 + cBase + c;
                        valid = (gj <= gi);
                    }
                    p[r][c] = valid ? __expf(s[r][c] * scale - m[r]) * invl[r] : 0.f;
                }
                float4 pv = make_float4(p[r][0], p[r][1], p[r][2], p[r][3]);
                *(float4*)(attp + (size_t)(iBase + r) * Tn + kt * 64 + cBase) = pv;
                #pragma unroll
                for (int c = 0; c < 4; c++)
                    Ps[(cBase + c) * SST + iBase + r] = p[r][c];
            }
            __syncthreads();

            #pragma unroll 16
            for (int j = 0; j < 64; j++) {
                const float* prow = Ps + j * SST;
                const float* vrow = Vs + j * SST;
                float2 pa = *(const float2*)(prow + iBase);
                float2 pb = *(const float2*)(prow + iBase + 2);
                float2 va = *(const float2*)(vrow + cBase);
                float2 vb = *(const float2*)(vrow + cBase + 2);
                float pr[4] = {pa.x, pa.y, pb.x, pb.y};
                float vv[4] = {va.x, va.y, vb.x, vb.y};
                #pragma unroll
                for (int r = 0; r < 4; r++)
                    #pragma unroll
                    for (int c = 0; c < 4; c++)
                        yacc[r][c] += pr[r] * vv[c];
            }
        } else {
            const float4 z = make_float4(0.f, 0.f, 0.f, 0.f);
            #pragma unroll
            for (int r = 0; r < 4; r++)
                *(float4*)(attp + (size_t)(iBase + r) * Tn + kt * 64 + cBase) = z;
        }
    }

    const int b = bh >> 4, h = bh & 15;
    #pragma unroll
    for (int r = 0; r < 4; r++) {
        const int t = qbase + iBase + r;
        float4 yv = make_float4(yacc[r][0], yacc[r][1], yacc[r][2], yacc[r][3]);
        *(float4*)(g_y + ((size_t)(b * Tn + t)) * Cn + h * Dn + cBase) = yv;
    }
}

// ---------------------------------------------------------------------------
extern "C" void kernel_launch(void* const* d_in, const int* in_sizes, int n_in,
                              void* d_out, int out_size)
{
    const float* x  = (const float*)d_in[0];
    const float* Wq = (const float*)d_in[1];
    const float* bq = (const float*)d_in[2];
    const float* Wk = (const float*)d_in[3];
    const float* bk = (const float*)d_in[4];
    const float* Wv = (const float*)d_in[5];
    const float* bv = (const float*)d_in[6];
    const float* Wp = (const float*)d_in[7];
    const float* bp = (const float*)d_in[8];

    float* y_out   = (float*)d_out;                       // [B,T,C]
    float* att_out = y_out + (size_t)BT * Cn;             // [B,H,T,T]

    cudaFuncSetAttribute(gemm_qkv_tc,  cudaFuncAttributeMaxDynamicSharedMemorySize, GEMM_SMEM);
    cudaFuncSetAttribute(gemm_proj_tc, cudaFuncAttributeMaxDynamicSharedMemorySize, GEMM_SMEM);

    // QKV projections (bf16-split mma.sync)
    gemm_qkv_tc<<<dim3(8, 64, 3), 256, GEMM_SMEM>>>(x, Wq, bq, Wk, bk, Wv, bv);

    // Fused attention (scores -> softmax -> att write -> att@V)
    const int smem = 4 * 64 * SST * (int)sizeof(float);   // 67584 B
    cudaFuncSetAttribute(attn_kernel, cudaFuncAttributeMaxDynamicSharedMemorySize, smem);
    attn_kernel<<<dim3(NTILES, Bn * Hn), 256, smem>>>(att_out);

    // Output projection (bf16-split mma.sync)
    gemm_proj_tc<<<dim3(8, 64), 256, GEMM_SMEM>>>(Wp, bp, y_out);
}

// round 5
// speedup vs baseline: 3.9708x; 1.9991x over previous
#include <cuda_runtime.h>
#include <cuda_bf16.h>
#include <math_constants.h>
#include <cstdint>

#define Bn 4
#define Tn 2048
#define Cn 1024
#define Hn 16
#define Dn 64
#define BT (Bn*Tn)      // 8192
#define NQT (Tn/128)    // 16 q-tiles of 128

typedef unsigned short ushort_t;

// Scratch (device globals — no allocation allowed)
__device__ __align__(16) ushort_t g_qh[(size_t)64*Tn*Dn];   // bf16 hi/lo of q (pre-scaled by 0.125)
__device__ __align__(16) ushort_t g_ql[(size_t)64*Tn*Dn];
__device__ __align__(16) ushort_t g_kh[(size_t)64*Tn*Dn];
__device__ __align__(16) ushort_t g_kl[(size_t)64*Tn*Dn];
__device__ __align__(16) ushort_t g_vh[(size_t)64*Tn*Dn];
__device__ __align__(16) ushort_t g_vl[(size_t)64*Tn*Dn];
__device__ float g_y[(size_t)BT*Cn];      // attention output (normalized), [b*T+t, C]
__device__ float g_lsum[(size_t)64*Tn];   // softmax row sums

// ---------------------------------------------------------------------------
// common helpers
// ---------------------------------------------------------------------------
__device__ __forceinline__ uint32_t smem_u32(const void* p) {
    uint32_t a;
    asm("{ .reg .u64 t; cvta.to.shared.u64 t, %1; cvt.u32.u64 %0, t; }"
        : "=r"(a) : "l"(p));
    return a;
}

__device__ __forceinline__ void split2(float f0, float f1, uint32_t& hi, uint32_t& lo) {
    __nv_bfloat16 h0 = __float2bfloat16(f0);
    __nv_bfloat16 h1 = __float2bfloat16(f1);
    __nv_bfloat16 l0 = __float2bfloat16(f0 - __bfloat162float(h0));
    __nv_bfloat16 l1 = __float2bfloat16(f1 - __bfloat162float(h1));
    hi = (uint32_t)__bfloat16_as_ushort(h0) | ((uint32_t)__bfloat16_as_ushort(h1) << 16);
    lo = (uint32_t)__bfloat16_as_ushort(l0) | ((uint32_t)__bfloat16_as_ushort(l1) << 16);
}

__device__ __forceinline__ void ldm_x4(uint32_t r[4], uint32_t addr) {
    asm volatile("ldmatrix.sync.aligned.m8n8.x4.shared.b16 {%0,%1,%2,%3}, [%4];"
        : "=r"(r[0]), "=r"(r[1]), "=r"(r[2]), "=r"(r[3]) : "r"(addr));
}

__device__ __forceinline__ void ldm_x4_t(uint32_t r[4], uint32_t addr) {
    asm volatile("ldmatrix.sync.aligned.m8n8.x4.trans.shared.b16 {%0,%1,%2,%3}, [%4];"
        : "=r"(r[0]), "=r"(r[1]), "=r"(r[2]), "=r"(r[3]) : "r"(addr));
}

__device__ __forceinline__ void mma_bf16(float d[4], const uint32_t a[4], const uint32_t b[2]) {
    asm volatile(
        "mma.sync.aligned.m16n8k16.row.col.f32.bf16.bf16.f32 "
        "{%0,%1,%2,%3}, {%4,%5,%6,%7}, {%8,%9}, {%0,%1,%2,%3};"
        : "+f"(d[0]), "+f"(d[1]), "+f"(d[2]), "+f"(d[3])
        : "r"(a[0]), "r"(a[1]), "r"(a[2]), "r"(a[3]), "r"(b[0]), "r"(b[1]));
}

#define CP16(dst, src) asm volatile("cp.async.cg.shared.global [%0], [%1], 16;" :: "r"(dst), "l"(src))
#define CPCOMMIT()     asm volatile("cp.async.commit_group;" ::: "memory")
#define CPWAIT0()      asm volatile("cp.async.wait_group 0;" ::: "memory")
#define CPWAIT1()      asm volatile("cp.async.wait_group 1;" ::: "memory")

// ===========================================================================
// bf16-split mma.sync GEMM (R4 structure): out = A@W + bias
// REMAP=true: write bf16 hi/lo (scaled) to [bh][t][d] layout arrays
// ===========================================================================
#define APITCH 80
#define BPITCH 272
#define AL_OFF 10240
#define BH_OFF 20480
#define BL_OFF 29184
#define STAGE_B 37888
#define GEMM_SMEM (2*STAGE_B)

template<bool REMAP>
__device__ __forceinline__ void gemm_mma_body(
    const float* __restrict__ A, const float* __restrict__ W,
    const float* __restrict__ bias, float* __restrict__ out,
    ushort_t* __restrict__ outH, ushort_t* __restrict__ outL, float scl)
{
    extern __shared__ char smc[];

    const int tid  = threadIdx.x;
    const int wid  = tid >> 5;
    const int lane = tid & 31;
    const int bm = blockIdx.y, bn = blockIdx.x;
    const int warp_m = wid & 3;
    const int warp_n = wid >> 2;

    const int aM0 = tid >> 3;
    const int aQ  = tid & 7;
    const int bK0 = tid >> 5;
    const int bNq = tid & 31;

    const float* Abase = A + (size_t)(bm * 128) * 1024;
    const float* Wbase = W + (size_t)(bn * 128);

    const uint32_t sb = smem_u32(smc);
    const int l15 = lane & 15;
    const int lhi = lane >> 4;
    const uint32_t aBase = sb + (uint32_t)((warp_m * 32 + l15) * APITCH + lhi * 16);
    const uint32_t bBase = sb + BH_OFF + (uint32_t)(l15 * BPITCH + warp_n * 128 + lhi * 16);

    float d[2][8][4];
    #pragma unroll
    for (int t = 0; t < 2; t++)
        #pragma unroll
        for (int u = 0; u < 8; u++)
            #pragma unroll
            for (int v = 0; v < 4; v++) d[t][u][v] = 0.f;

    float4 rA[4], rB[4];
    #pragma unroll
    for (int i = 0; i < 4; i++) {
        rA[i] = *(const float4*)(Abase + (size_t)(aM0 + 32 * i) * 1024 + 4 * aQ);
        rB[i] = *(const float4*)(Wbase + (size_t)(bK0 + 8 * i) * 1024 + 4 * bNq);
    }

    for (int kc = 0; kc < 32; kc++) {
        const int stg = kc & 1;
        char* s = smc + stg * STAGE_B;
        const uint32_t stgOff = stg * STAGE_B;

        #pragma unroll
        for (int i = 0; i < 4; i++) {
            const int m = aM0 + 32 * i;
            uint32_t h0, l0, h1, l1;
            split2(rA[i].x, rA[i].y, h0, l0);
            split2(rA[i].z, rA[i].w, h1, l1);
            *(uint2*)(s + m * APITCH + aQ * 8)          = make_uint2(h0, h1);
            *(uint2*)(s + AL_OFF + m * APITCH + aQ * 8) = make_uint2(l0, l1);

            const int k = bK0 + 8 * i;
            split2(rB[i].x, rB[i].y, h0, l0);
            split2(rB[i].z, rB[i].w, h1, l1);
            *(uint2*)(s + BH_OFF + k * BPITCH + bNq * 8) = make_uint2(h0, h1);
            *(uint2*)(s + BL_OFF + k * BPITCH + bNq * 8) = make_uint2(l0, l1);
        }
        __syncthreads();

        if (kc < 31) {
            const float* An = Abase + (kc + 1) * 32;
            const float* Wn = Wbase + (size_t)((kc + 1) * 32) * 1024;
            #pragma unroll
            for (int i = 0; i < 4; i++) {
                rA[i] = *(const float4*)(An + (size_t)(aM0 + 32 * i) * 1024 + 4 * aQ);
                rB[i] = *(const float4*)(Wn + (size_t)(bK0 + 8 * i) * 1024 + 4 * bNq);
            }
        }

        #pragma unroll
        for (int ss = 0; ss < 2; ss++) {
            uint32_t Ah[2][4], Al_[2][4];
            #pragma unroll
            for (int t = 0; t < 2; t++) {
                const uint32_t aa = aBase + stgOff + (uint32_t)(t * 16 * APITCH + ss * 32);
                ldm_x4(Ah[t], aa);
                ldm_x4(Al_[t], aa + AL_OFF);
            }
            #pragma unroll
            for (int half = 0; half < 2; half++) {
                uint32_t Bh[4][2], Bl[4][2];
                #pragma unroll
                for (int gp = 0; gp < 2; gp++) {
                    const int g2 = half * 2 + gp;
                    const uint32_t ba = bBase + stgOff + (uint32_t)(ss * 16 * BPITCH + g2 * 32);
                    uint32_t r[4];
                    ldm_x4_t(r, ba);
                    Bh[gp*2][0] = r[0]; Bh[gp*2][1] = r[1];
                    Bh[gp*2+1][0] = r[2]; Bh[gp*2+1][1] = r[3];
                    ldm_x4_t(r, ba + (BL_OFF - BH_OFF));
                    Bl[gp*2][0] = r[0]; Bl[gp*2][1] = r[1];
                    Bl[gp*2+1][0] = r[2]; Bl[gp*2+1][1] = r[3];
                }
                #pragma unroll
                for (int t = 0; t < 2; t++)
                    #pragma unroll
                    for (int u = 0; u < 4; u++) {
                        const int un = half * 4 + u;
                        mma_bf16(d[t][un], Ah[t], Bh[u]);
                        mma_bf16(d[t][un], Ah[t], Bl[u]);
                        mma_bf16(d[t][un], Al_[t], Bh[u]);
                    }
            }
        }
    }

    #pragma unroll
    for (int t = 0; t < 2; t++) {
        const int rowA = bm * 128 + warp_m * 32 + t * 16 + (lane >> 2);
        #pragma unroll
        for (int half = 0; half < 2; half++) {
            const int m = rowA + half * 8;
            #pragma unroll
            for (int u = 0; u < 8; u++) {
                const int col = bn * 128 + warp_n * 64 + u * 8 + ((lane & 3) << 1);
                const float v0 = d[t][u][half * 2 + 0] + __ldg(&bias[col]);
                const float v1 = d[t][u][half * 2 + 1] + __ldg(&bias[col + 1]);
                if (REMAP) {
                    const int b = m >> 11, tt = m & 2047;
                    const int h = col >> 6, d0 = col & 63;
                    const size_t idx = (((size_t)(b * Hn + h) * Tn) + tt) * Dn + d0;
                    uint32_t hh, ll;
                    split2(v0 * scl, v1 * scl, hh, ll);
                    *(uint32_t*)(outH + idx) = hh;
                    *(uint32_t*)(outL + idx) = ll;
                } else {
                    *(float2*)(out + (size_t)m * 1024 + col) = make_float2(v0, v1);
                }
            }
        }
    }
}

__global__ __launch_bounds__(256) void gemm_qkv_tc(
    const float* __restrict__ X,
    const float* __restrict__ Wq, const float* __restrict__ bq,
    const float* __restrict__ Wk, const float* __restrict__ bk,
    const float* __restrict__ Wv, const float* __restrict__ bv)
{
    const float* W; const float* bias; ushort_t *oh, *ol; float scl;
    if (blockIdx.z == 0)      { W = Wq; bias = bq; oh = g_qh; ol = g_ql; scl = 0.125f; }
    else if (blockIdx.z == 1) { W = Wk; bias = bk; oh = g_kh; ol = g_kl; scl = 1.f; }
    else                      { W = Wv; bias = bv; oh = g_vh; ol = g_vl; scl = 1.f; }
    gemm_mma_body<true>(X, W, bias, nullptr, oh, ol, scl);
}

__global__ __launch_bounds__(256) void gemm_proj_tc(
    const float* __restrict__ Wp, const float* __restrict__ bp,
    float* __restrict__ out)
{
    gemm_mma_body<false>(g_y, Wp, bp, out, nullptr, nullptr, 1.f);
}

// ===========================================================================
// MMA attention: CTA = (bh, 128-q-tile), 8 warps, warp owns 16 full rows.
// Single pass, no-max softmax: write E = exp(s) unnormalized + row sums,
// y = (E@V)/l in-kernel.  K/V pre-split bf16 hi/lo, cp.async double buffer.
// ===========================================================================
#define ATT_SMEM 131072
#define AKH 0
#define AKL 16384
#define AVH 32768
#define AVL 49152

__global__ __launch_bounds__(256, 1) void attn_mma(float* __restrict__ att)
{
    extern __shared__ char smc[];
    const uint32_t sb = smem_u32(smc);
    const int tid = threadIdx.x, wid = tid >> 5, lane = tid & 31;
    const int bh = blockIdx.y;
    const int qt = (NQT - 1) - blockIdx.x;   // big tiles first
    const int qbase = qt * 128;
    const int nkt = qt + 1;

    const ushort_t* qh = g_qh + ((size_t)bh * Tn + qbase) * Dn;
    const ushort_t* ql = g_ql + ((size_t)bh * Tn + qbase) * Dn;
    const ushort_t* khp = g_kh + (size_t)bh * Tn * Dn;
    const ushort_t* klp = g_kl + (size_t)bh * Tn * Dn;
    const ushort_t* vhp = g_vh + (size_t)bh * Tn * Dn;
    const ushort_t* vlp = g_vl + (size_t)bh * Tn * Dn;
    float* attp = att + ((size_t)bh * Tn + qbase) * Tn;

    // ---- zero-fill strict-upper tiles (att poisoned by harness) ----
    const int zstart = nkt * 128;
    #pragma unroll 1
    for (int rg = 0; rg < 16; rg++) {
        const int r = rg * 8 + wid;
        for (int c = zstart + lane * 4; c < Tn; c += 128)
            *(float4*)(attp + (size_t)r * Tn + c) = make_float4(0.f, 0.f, 0.f, 0.f);
    }

    // ---- Q stage into buffer0 (KH/KL slots) ----
    #pragma unroll
    for (int i = 0; i < 4; i++) {
        const int idx = tid + 256 * i;
        const int r = idx >> 3, c = idx & 7;
        const uint32_t off = (uint32_t)(r * 128 + ((c ^ (r & 7)) << 4));
        CP16(sb + AKH + off, qh + r * 64 + c * 8);
        CP16(sb + AKL + off, ql + r * 64 + c * 8);
    }
    CPCOMMIT();

    // ---- issue K/V tile 0 into buffer1 ----
    {
        const uint32_t base = sb + 65536;
        #pragma unroll
        for (int i = 0; i < 4; i++) {
            const int idx = tid + 256 * i;
            const int r = idx >> 3, c = idx & 7;
            const uint32_t off = (uint32_t)(r * 128 + ((c ^ (r & 7)) << 4));
            const size_t so = (size_t)r * 64 + c * 8;
            CP16(base + AKH + off, khp + so);
            CP16(base + AKL + off, klp + so);
            CP16(base + AVH + off, vhp + so);
            CP16(base + AVL + off, vlp + so);
        }
        CPCOMMIT();
    }

    CPWAIT1();
    __syncthreads();

    // ---- load Q fragments ----
    uint32_t q_h[4][4], q_l[4][4];
    {
        const int arow = 16 * wid + ((lane >> 3) & 1) * 8 + (lane & 7);
        #pragma unroll
        for (int kk = 0; kk < 4; kk++) {
            const uint32_t addr = sb + AKH + (uint32_t)(arow * 128 +
                (((2 * kk + (lane >> 4)) ^ (arow & 7)) << 4));
            ldm_x4(q_h[kk], addr);
            ldm_x4(q_l[kk], addr + 16384);
        }
    }
    __syncthreads();   // buffer0 free for tile 1

    // lane constants for K (B of S) and V (B of AV) ldmatrix
    const int bkeyL = ((lane >> 4) << 3) + (lane & 7);
    const int bchk  = (lane >> 3) & 1;
    const uint32_t brow = (uint32_t)(bkeyL * 128);
    const int bsw = bkeyL & 7;

    const int vkeyL = ((lane >> 3) & 1) * 8 + (lane & 7);
    const int vchk  = lane >> 4;
    const uint32_t vrow = (uint32_t)(vkeyL * 128);
    const int vsw = vkeyL & 7;

    const int rl0 = 16 * wid + (lane >> 2);
    const int cl0 = 2 * (lane & 3);

    float d_y[8][4];
    #pragma unroll
    for (int j = 0; j < 8; j++)
        #pragma unroll
        for (int v = 0; v < 4; v++) d_y[j][v] = 0.f;
    float lsum0 = 0.f, lsum1 = 0.f;

    for (int kt = 0; kt < nkt; kt++) {
        const int buf = (kt + 1) & 1;
        if (kt + 1 < nkt) {
            const uint32_t base = sb + (uint32_t)((kt & 1) * 65536);
            const size_t tof = (size_t)(kt + 1) * 128 * 64;
            #pragma unroll
            for (int i = 0; i < 4; i++) {
                const int idx = tid + 256 * i;
                const int r = idx >> 3, c = idx & 7;
                const uint32_t off = (uint32_t)(r * 128 + ((c ^ (r & 7)) << 4));
                const size_t so = tof + (size_t)r * 64 + c * 8;
                CP16(base + AKH + off, khp + so);
                CP16(base + AKL + off, klp + so);
                CP16(base + AVH + off, vhp + so);
                CP16(base + AVL + off, vlp + so);
            }
            CPCOMMIT();
            CPWAIT1();
        } else {
            CPWAIT0();
        }
        __syncthreads();

        const uint32_t base = sb + (uint32_t)(buf * 65536);

        // ---- S = Q @ K^T (3-term) ----
        float ds[16][4];
        #pragma unroll
        for (int j = 0; j < 16; j++)
            #pragma unroll
            for (int v = 0; v < 4; v++) ds[j][v] = 0.f;

        #pragma unroll
        for (int kk = 0; kk < 4; kk++) {
            #pragma unroll
            for (int j16 = 0; j16 < 8; j16++) {
                const uint32_t ka = base + AKH + (uint32_t)(j16 * 2048) + brow +
                                    (uint32_t)((((kk << 1) | bchk) ^ bsw) << 4);
                uint32_t khf[4], klf[4];
                ldm_x4(khf, ka);
                ldm_x4(klf, ka + 16384);
                uint32_t b0h[2] = {khf[0], khf[1]}, b1h[2] = {khf[2], khf[3]};
                uint32_t b0l[2] = {klf[0], klf[1]}, b1l[2] = {klf[2], klf[3]};
                mma_bf16(ds[2*j16],   q_h[kk], b0h);
                mma_bf16(ds[2*j16],   q_h[kk], b0l);
                mma_bf16(ds[2*j16],   q_l[kk], b0h);
                mma_bf16(ds[2*j16+1], q_h[kk], b1h);
                mma_bf16(ds[2*j16+1], q_h[kk], b1l);
                mma_bf16(ds[2*j16+1], q_l[kk], b1h);
            }
        }

        // ---- exp, causal mask (diag tile), att store, row sums ----
        const bool diag = (kt == qt);
        const int ktbase = kt * 128;
        #pragma unroll
        for (int j = 0; j < 16; j++) {
            const int c = 8 * j + cl0;
            float e00 = __expf(ds[j][0]);
            float e01 = __expf(ds[j][1]);
            float e10 = __expf(ds[j][2]);
            float e11 = __expf(ds[j][3]);
            if (diag) {
                if (c     > rl0)     e00 = 0.f;
                if (c + 1 > rl0)     e01 = 0.f;
                if (c     > rl0 + 8) e10 = 0.f;
                if (c + 1 > rl0 + 8) e11 = 0.f;
            }
            ds[j][0] = e00; ds[j][1] = e01; ds[j][2] = e10; ds[j][3] = e11;
            *(float2*)(attp + (size_t)rl0 * Tn + ktbase + c)       = make_float2(e00, e01);
            *(float2*)(attp + (size_t)(rl0 + 8) * Tn + ktbase + c) = make_float2(e10, e11);
            lsum0 += e00 + e01;
            lsum1 += e10 + e11;
        }

        // ---- Y += P @ V (P from fragments, 3-term) ----
        #pragma unroll
        for (int kap = 0; kap < 8; kap++) {
            uint32_t p_h[4], p_l[4];
            split2(ds[2*kap][0],   ds[2*kap][1],   p_h[0], p_l[0]);
            split2(ds[2*kap][2],   ds[2*kap][3],   p_h[1], p_l[1]);
            split2(ds[2*kap+1][0], ds[2*kap+1][1], p_h[2], p_l[2]);
            split2(ds[2*kap+1][2], ds[2*kap+1][3], p_h[3], p_l[3]);
            #pragma unroll
            for (int j16 = 0; j16 < 4; j16++) {
                const uint32_t va = base + AVH + (uint32_t)(kap * 2048) + vrow +
                                    (uint32_t)((((j16 << 1) | vchk) ^ vsw) << 4);
                uint32_t vhf[4], vlf[4];
                ldm_x4_t(vhf, va);
                ldm_x4_t(vlf, va + 16384);
                uint32_t v0h[2] = {vhf[0], vhf[1]}, v1h[2] = {vhf[2], vhf[3]};
                uint32_t v0l[2] = {vlf[0], vlf[1]}, v1l[2] = {vlf[2], vlf[3]};
                mma_bf16(d_y[2*j16],   p_h, v0h);
                mma_bf16(d_y[2*j16],   p_h, v0l);
                mma_bf16(d_y[2*j16],   p_l, v0h);
                mma_bf16(d_y[2*j16+1], p_h, v1h);
                mma_bf16(d_y[2*j16+1], p_h, v1l);
                mma_bf16(d_y[2*j16+1], p_l, v1h);
            }
        }
        __syncthreads();
    }

    // ---- finalize: row sums, 1/l, write y ----
    lsum0 += __shfl_xor_sync(0xffffffffu, lsum0, 1);
    lsum0 += __shfl_xor_sync(0xffffffffu, lsum0, 2);
    lsum1 += __shfl_xor_sync(0xffffffffu, lsum1, 1);
    lsum1 += __shfl_xor_sync(0xffffffffu, lsum1, 2);
    const float inv0 = 1.f / lsum0;
    const float inv1 = 1.f / lsum1;
    if ((lane & 3) == 0) {
        g_lsum[(size_t)bh * Tn + qbase + rl0]     = lsum0;
        g_lsum[(size_t)bh * Tn + qbase + rl0 + 8] = lsum1;
    }
    const int b = bh >> 4, hh = bh & 15;
    float* y0 = g_y + ((size_t)(b * Tn + qbase + rl0)) * Cn + hh * 64;
    float* y1 = y0 + 8 * Cn;
    #pragma unroll
    for (int j = 0; j < 8; j++) {
        *(float2*)(y0 + 8 * j + cl0) = make_float2(d_y[j][0] * inv0, d_y[j][1] * inv0);
        *(float2*)(y1 + 8 * j + cl0) = make_float2(d_y[j][2] * inv1, d_y[j][3] * inv1);
    }
}

// ---------------------------------------------------------------------------
// Normalize att rows by 1/l (lower-triangle region only). Warp per row.
// ---------------------------------------------------------------------------
__global__ __launch_bounds__(256) void norm_att(float* __restrict__ att)
{
    const int wid = threadIdx.x >> 5, lane = threadIdx.x & 31;
    const size_t row = (size_t)blockIdx.x * 8 + wid;
    const int rs = (int)(row & (Tn - 1));
    const int width = ((rs >> 7) + 1) * 128;
    const float inv = 1.f / g_lsum[row];
    float* p = att + row * Tn;
    for (int c = lane * 4; c < width; c += 128) {
        float4 v = *(float4*)(p + c);
        v.x *= inv; v.y *= inv; v.z *= inv; v.w *= inv;
        *(float4*)(p + c) = v;
    }
}

// ---------------------------------------------------------------------------
extern "C" void kernel_launch(void* const* d_in, const int* in_sizes, int n_in,
                              void* d_out, int out_size)
{
    const float* x  = (const float*)d_in[0];
    const float* Wq = (const float*)d_in[1];
    const float* bq = (const float*)d_in[2];
    const float* Wk = (const float*)d_in[3];
    const float* bk = (const float*)d_in[4];
    const float* Wv = (const float*)d_in[5];
    const float* bv = (const float*)d_in[6];
    const float* Wp = (const float*)d_in[7];
    const float* bp = (const float*)d_in[8];

    float* y_out   = (float*)d_out;                       // [B,T,C]
    float* att_out = y_out + (size_t)BT * Cn;             // [B,H,T,T]

    cudaFuncSetAttribute(gemm_qkv_tc,  cudaFuncAttributeMaxDynamicSharedMemorySize, GEMM_SMEM);
    cudaFuncSetAttribute(gemm_proj_tc, cudaFuncAttributeMaxDynamicSharedMemorySize, GEMM_SMEM);
    cudaFuncSetAttribute(attn_mma,     cudaFuncAttributeMaxDynamicSharedMemorySize, ATT_SMEM);

    // QKV projections -> bf16 hi/lo q,k,v (q pre-scaled by 1/8)
    gemm_qkv_tc<<<dim3(8, 64, 3), 256, GEMM_SMEM>>>(x, Wq, bq, Wk, bk, Wv, bv);

    // Fused MMA attention: unnormalized E -> att, row sums, y = E@V / l
    attn_mma<<<dim3(NQT, Bn * Hn), 256, ATT_SMEM>>>(att_out);

    // Normalize att lower triangle by 1/l
    norm_att<<<(64 * Tn) / 8, 256>>>(att_out);

    // Output projection
    gemm_proj_tc<<<dim3(8, 64), 256, GEMM_SMEM>>>(Wp, bp, y_out);
}

// round 6
// speedup vs baseline: 4.0694x; 1.0248x over previous
#include <cuda_runtime.h>
#include <cuda_bf16.h>
#include <math_constants.h>
#include <cstdint>

#define Bn 4
#define Tn 2048
#define Cn 1024
#define Hn 16
#define Dn 64
#define BT (Bn*Tn)      // 8192
#define NQT (Tn/128)    // 16 q-tiles of 128

typedef unsigned short ushort_t;

// Scratch (device globals — no allocation allowed)
__device__ __align__(16) ushort_t g_qh[(size_t)64*Tn*Dn];   // bf16 hi/lo of q (pre-scaled 0.125)
__device__ __align__(16) ushort_t g_ql[(size_t)64*Tn*Dn];
__device__ __align__(16) ushort_t g_kh[(size_t)64*Tn*Dn];
__device__ __align__(16) ushort_t g_kl[(size_t)64*Tn*Dn];
__device__ __align__(16) ushort_t g_vh[(size_t)64*Tn*Dn];
__device__ __align__(16) ushort_t g_vl[(size_t)64*Tn*Dn];
__device__ __align__(16) ushort_t g_xh[(size_t)BT*Cn];      // x pre-split
__device__ __align__(16) ushort_t g_xl[(size_t)BT*Cn];
__device__ __align__(16) ushort_t g_wh[(size_t)4*Cn*Cn];    // Wq,Wk,Wv,Wp pre-split
__device__ __align__(16) ushort_t g_wl[(size_t)4*Cn*Cn];
__device__ __align__(16) ushort_t g_yh[(size_t)BT*Cn];      // attention out (normalized), pre-split
__device__ __align__(16) ushort_t g_yl[(size_t)BT*Cn];
__device__ float g_lsum[(size_t)64*Tn];                     // softmax row sums

// ---------------------------------------------------------------------------
// helpers
// ---------------------------------------------------------------------------
__device__ __forceinline__ uint32_t smem_u32(const void* p) {
    uint32_t a;
    asm("{ .reg .u64 t; cvta.to.shared.u64 t, %1; cvt.u32.u64 %0, t; }"
        : "=r"(a) : "l"(p));
    return a;
}

__device__ __forceinline__ void split2(float f0, float f1, uint32_t& hi, uint32_t& lo) {
    __nv_bfloat16 h0 = __float2bfloat16(f0);
    __nv_bfloat16 h1 = __float2bfloat16(f1);
    __nv_bfloat16 l0 = __float2bfloat16(f0 - __bfloat162float(h0));
    __nv_bfloat16 l1 = __float2bfloat16(f1 - __bfloat162float(h1));
    hi = (uint32_t)__bfloat16_as_ushort(h0) | ((uint32_t)__bfloat16_as_ushort(h1) << 16);
    lo = (uint32_t)__bfloat16_as_ushort(l0) | ((uint32_t)__bfloat16_as_ushort(l1) << 16);
}

__device__ __forceinline__ void ldm_x4(uint32_t r[4], uint32_t addr) {
    asm volatile("ldmatrix.sync.aligned.m8n8.x4.shared.b16 {%0,%1,%2,%3}, [%4];"
        : "=r"(r[0]), "=r"(r[1]), "=r"(r[2]), "=r"(r[3]) : "r"(addr));
}

__device__ __forceinline__ void ldm_x4_t(uint32_t r[4], uint32_t addr) {
    asm volatile("ldmatrix.sync.aligned.m8n8.x4.trans.shared.b16 {%0,%1,%2,%3}, [%4];"
        : "=r"(r[0]), "=r"(r[1]), "=r"(r[2]), "=r"(r[3]) : "r"(addr));
}

__device__ __forceinline__ void mma_bf16(float d[4], const uint32_t a[4], const uint32_t b[2]) {
    asm volatile(
        "mma.sync.aligned.m16n8k16.row.col.f32.bf16.bf16.f32 "
        "{%0,%1,%2,%3}, {%4,%5,%6,%7}, {%8,%9}, {%0,%1,%2,%3};"
        : "+f"(d[0]), "+f"(d[1]), "+f"(d[2]), "+f"(d[3])
        : "r"(a[0]), "r"(a[1]), "r"(a[2]), "r"(a[3]), "r"(b[0]), "r"(b[1]));
}

#define CP16(dst, src) asm volatile("cp.async.cg.shared.global [%0], [%1], 16;" :: "r"(dst), "l"(src))
#define CPCOMMIT()     asm volatile("cp.async.commit_group;" ::: "memory")
#define CPWAIT0()      asm volatile("cp.async.wait_group 0;" ::: "memory")
#define CPWAIT1()      asm volatile("cp.async.wait_group 1;" ::: "memory")

// ---------------------------------------------------------------------------
// pre-convert kernels: fp32 -> bf16 hi/lo
// ---------------------------------------------------------------------------
__global__ __launch_bounds__(256) void conv_x(const float4* __restrict__ src)
{
    const int i = blockIdx.x * 256 + threadIdx.x;   // n4 = BT*Cn/4 = 2097152
    float4 v = src[i];
    uint32_t h0, l0, h1, l1;
    split2(v.x, v.y, h0, l0);
    split2(v.z, v.w, h1, l1);
    ((uint2*)g_xh)[i] = make_uint2(h0, h1);
    ((uint2*)g_xl)[i] = make_uint2(l0, l1);
}

__global__ __launch_bounds__(256) void conv_w(
    const float* __restrict__ Wq, const float* __restrict__ Wk,
    const float* __restrict__ Wv, const float* __restrict__ Wp)
{
    const int z = blockIdx.y;
    const float4* src = (const float4*)(z == 0 ? Wq : z == 1 ? Wk : z == 2 ? Wv : Wp);
    uint2* dh = (uint2*)(g_wh + (size_t)z * Cn * Cn);
    uint2* dl = (uint2*)(g_wl + (size_t)z * Cn * Cn);
    const int i = blockIdx.x * 256 + threadIdx.x;   // n4 = 262144
    float4 v = src[i];
    uint32_t h0, l0, h1, l1;
    split2(v.x, v.y, h0, l0);
    split2(v.z, v.w, h1, l1);
    dh[i] = make_uint2(h0, h1);
    dl[i] = make_uint2(l0, l1);
}

// ===========================================================================
// bf16 pre-split GEMM, cp.async 3-stage pipeline.
// out = A@W + bias.  A: [M][1024] bf16 hi/lo.  W: [1024][1024] bf16 hi/lo.
// CTA 128x128, BK=32, 8 warps (4m x 2n), m16n8k16, 3-term emulation.
// Stage SMEM: Ah@0 (128x80B), Al@10240, Bh@20480 (32x272B), Bl@29184.
// ===========================================================================
#define GSTG 37888
#define GEMM_SMEM (3*GSTG)   // 113664

__device__ __forceinline__ void gemm_issue(
    uint32_t sbase,
    const ushort_t* __restrict__ Ah_g, const ushort_t* __restrict__ Al_g,
    const ushort_t* __restrict__ Bh_g, const ushort_t* __restrict__ Bl_g,
    int bm, int bn, int kc, int tid)
{
    #pragma unroll
    for (int i = 0; i < 2; i++) {
        const int ia = tid + 256 * i;
        const int r = ia >> 2, c = ia & 3;
        const uint32_t dst = sbase + (uint32_t)(r * 80 + c * 16);
        const size_t src = (size_t)(bm * 128 + r) * 1024 + kc * 32 + c * 8;
        CP16(dst, Ah_g + src);
        CP16(dst + 10240, Al_g + src);
    }
    #pragma unroll
    for (int i = 0; i < 2; i++) {
        const int ib = tid + 256 * i;
        const int k = ib >> 4, c = ib & 15;
        const uint32_t dst = sbase + (uint32_t)(20480 + k * 272 + c * 16);
        const size_t src = (size_t)(kc * 32 + k) * 1024 + bn * 128 + c * 8;
        CP16(dst, Bh_g + src);
        CP16(dst + 8704, Bl_g + src);
    }
    CPCOMMIT();
}

template<bool REMAP>
__device__ __forceinline__ void gemm2_body(
    const ushort_t* __restrict__ Ah_g, const ushort_t* __restrict__ Al_g,
    const ushort_t* __restrict__ Bh_g, const ushort_t* __restrict__ Bl_g,
    const float* __restrict__ bias, float* __restrict__ out,
    ushort_t* __restrict__ outH, ushort_t* __restrict__ outL, float scl)
{
    extern __shared__ char smc[];
    const uint32_t sb = smem_u32(smc);
    const int tid = threadIdx.x, wid = tid >> 5, lane = tid & 31;
    const int bm = blockIdx.y, bn = blockIdx.x;
    const int warp_m = wid & 3, warp_n = wid >> 2;

    const int l15 = lane & 15;
    const int lhi = lane >> 4;
    const uint32_t aBase = sb + (uint32_t)((warp_m * 32 + l15) * 80 + lhi * 16);
    const uint32_t bBase = sb + 20480 + (uint32_t)(l15 * 272 + warp_n * 128 + lhi * 16);

    float d[2][8][4];
    #pragma unroll
    for (int t = 0; t < 2; t++)
        #pragma unroll
        for (int u = 0; u < 8; u++)
            #pragma unroll
            for (int v = 0; v < 4; v++) d[t][u][v] = 0.f;

    gemm_issue(sb,        Ah_g, Al_g, Bh_g, Bl_g, bm, bn, 0, tid);
    gemm_issue(sb + GSTG, Ah_g, Al_g, Bh_g, Bl_g, bm, bn, 1, tid);

    for (int kc = 0; kc < 32; kc++) {
        if (kc == 31) { CPWAIT0(); } else { CPWAIT1(); }
        __syncthreads();
        if (kc < 30)
            gemm_issue(sb + (uint32_t)(((kc + 2) % 3) * GSTG),
                       Ah_g, Al_g, Bh_g, Bl_g, bm, bn, kc + 2, tid);

        const uint32_t stgOff = (uint32_t)((kc % 3) * GSTG);

        #pragma unroll
        for (int ss = 0; ss < 2; ss++) {
            uint32_t Ah[2][4], Al_[2][4];
            #pragma unroll
            for (int t = 0; t < 2; t++) {
                const uint32_t aa = aBase + stgOff + (uint32_t)(t * 16 * 80 + ss * 32);
                ldm_x4(Ah[t], aa);
                ldm_x4(Al_[t], aa + 10240);
            }
            #pragma unroll
            for (int half = 0; half < 2; half++) {
                uint32_t Bh[4][2], Bl[4][2];
                #pragma unroll
                for (int gp = 0; gp < 2; gp++) {
                    const int g2 = half * 2 + gp;
                    const uint32_t ba = bBase + stgOff + (uint32_t)(ss * 16 * 272 + g2 * 32);
                    uint32_t r[4];
                    ldm_x4_t(r, ba);
                    Bh[gp*2][0] = r[0]; Bh[gp*2][1] = r[1];
                    Bh[gp*2+1][0] = r[2]; Bh[gp*2+1][1] = r[3];
                    ldm_x4_t(r, ba + 8704);
                    Bl[gp*2][0] = r[0]; Bl[gp*2][1] = r[1];
                    Bl[gp*2+1][0] = r[2]; Bl[gp*2+1][1] = r[3];
                }
                #pragma unroll
                for (int t = 0; t < 2; t++)
                    #pragma unroll
                    for (int u = 0; u < 4; u++) {
                        const int un = half * 4 + u;
                        mma_bf16(d[t][un], Ah[t], Bh[u]);
                        mma_bf16(d[t][un], Ah[t], Bl[u]);
                        mma_bf16(d[t][un], Al_[t], Bh[u]);
                    }
            }
        }
    }

    // ---- epilogue ----
    #pragma unroll
    for (int t = 0; t < 2; t++) {
        const int rowA = bm * 128 + warp_m * 32 + t * 16 + (lane >> 2);
        #pragma unroll
        for (int half = 0; half < 2; half++) {
            const int m = rowA + half * 8;
            #pragma unroll
            for (int u = 0; u < 8; u++) {
                const int col = bn * 128 + warp_n * 64 + u * 8 + ((lane & 3) << 1);
                const float v0 = d[t][u][half * 2 + 0] + __ldg(&bias[col]);
                const float v1 = d[t][u][half * 2 + 1] + __ldg(&bias[col + 1]);
                if (REMAP) {
                    const int b = m >> 11, tt = m & 2047;
                    const int h = col >> 6, d0 = col & 63;
                    const size_t idx = (((size_t)(b * Hn + h) * Tn) + tt) * Dn + d0;
                    uint32_t hh, ll;
                    split2(v0 * scl, v1 * scl, hh, ll);
                    *(uint32_t*)(outH + idx) = hh;
                    *(uint32_t*)(outL + idx) = ll;
                } else {
                    *(float2*)(out + (size_t)m * 1024 + col) = make_float2(v0, v1);
                }
            }
        }
    }
}

__global__ __launch_bounds__(256) void gemm_qkv_tc(
    const float* __restrict__ bq, const float* __restrict__ bk,
    const float* __restrict__ bv)
{
    const float* bias; ushort_t *oh, *ol; float scl;
    if (blockIdx.z == 0)      { bias = bq; oh = g_qh; ol = g_ql; scl = 0.125f; }
    else if (blockIdx.z == 1) { bias = bk; oh = g_kh; ol = g_kl; scl = 1.f; }
    else                      { bias = bv; oh = g_vh; ol = g_vl; scl = 1.f; }
    const size_t wo = (size_t)blockIdx.z * Cn * Cn;
    gemm2_body<true>(g_xh, g_xl, g_wh + wo, g_wl + wo, bias, nullptr, oh, ol, scl);
}

__global__ __launch_bounds__(256) void gemm_proj_tc(
    const float* __restrict__ bp, float* __restrict__ out)
{
    const size_t wo = (size_t)3 * Cn * Cn;
    gemm2_body<false>(g_yh, g_yl, g_wh + wo, g_wl + wo, bp, out, nullptr, nullptr, 1.f);
}

// ===========================================================================
// MMA attention (R5): single pass, unnormalized E -> att, y = E@V / l.
// Epilogue now writes y as bf16 hi/lo for the proj GEMM.
// ===========================================================================
#define ATT_SMEM 131072
#define AKH 0
#define AKL 16384
#define AVH 32768
#define AVL 49152

__global__ __launch_bounds__(256, 1) void attn_mma(float* __restrict__ att)
{
    extern __shared__ char smc[];
    const uint32_t sb = smem_u32(smc);
    const int tid = threadIdx.x, wid = tid >> 5, lane = tid & 31;
    const int bh = blockIdx.y;
    const int qt = (NQT - 1) - blockIdx.x;
    const int qbase = qt * 128;
    const int nkt = qt + 1;

    const ushort_t* qh = g_qh + ((size_t)bh * Tn + qbase) * Dn;
    const ushort_t* ql = g_ql + ((size_t)bh * Tn + qbase) * Dn;
    const ushort_t* khp = g_kh + (size_t)bh * Tn * Dn;
    const ushort_t* klp = g_kl + (size_t)bh * Tn * Dn;
    const ushort_t* vhp = g_vh + (size_t)bh * Tn * Dn;
    const ushort_t* vlp = g_vl + (size_t)bh * Tn * Dn;
    float* attp = att + ((size_t)bh * Tn + qbase) * Tn;

    // zero-fill strict-upper tiles
    const int zstart = nkt * 128;
    #pragma unroll 1
    for (int rg = 0; rg < 16; rg++) {
        const int r = rg * 8 + wid;
        for (int c = zstart + lane * 4; c < Tn; c += 128)
            *(float4*)(attp + (size_t)r * Tn + c) = make_float4(0.f, 0.f, 0.f, 0.f);
    }

    // Q stage into buffer0
    #pragma unroll
    for (int i = 0; i < 4; i++) {
        const int idx = tid + 256 * i;
        const int r = idx >> 3, c = idx & 7;
        const uint32_t off = (uint32_t)(r * 128 + ((c ^ (r & 7)) << 4));
        CP16(sb + AKH + off, qh + r * 64 + c * 8);
        CP16(sb + AKL + off, ql + r * 64 + c * 8);
    }
    CPCOMMIT();

    // K/V tile 0 into buffer1
    {
        const uint32_t base = sb + 65536;
        #pragma unroll
        for (int i = 0; i < 4; i++) {
            const int idx = tid + 256 * i;
            const int r = idx >> 3, c = idx & 7;
            const uint32_t off = (uint32_t)(r * 128 + ((c ^ (r & 7)) << 4));
            const size_t so = (size_t)r * 64 + c * 8;
            CP16(base + AKH + off, khp + so);
            CP16(base + AKL + off, klp + so);
            CP16(base + AVH + off, vhp + so);
            CP16(base + AVL + off, vlp + so);
        }
        CPCOMMIT();
    }

    CPWAIT1();
    __syncthreads();

    uint32_t q_h[4][4], q_l[4][4];
    {
        const int arow = 16 * wid + ((lane >> 3) & 1) * 8 + (lane & 7);
        #pragma unroll
        for (int kk = 0; kk < 4; kk++) {
            const uint32_t addr = sb + AKH + (uint32_t)(arow * 128 +
                (((2 * kk + (lane >> 4)) ^ (arow & 7)) << 4));
            ldm_x4(q_h[kk], addr);
            ldm_x4(q_l[kk], addr + 16384);
        }
    }
    __syncthreads();

    const int bkeyL = ((lane >> 4) << 3) + (lane & 7);
    const int bchk  = (lane >> 3) & 1;
    const uint32_t brow = (uint32_t)(bkeyL * 128);
    const int bsw = bkeyL & 7;

    const int vkeyL = ((lane >> 3) & 1) * 8 + (lane & 7);
    const int vchk  = lane >> 4;
    const uint32_t vrow = (uint32_t)(vkeyL * 128);
    const int vsw = vkeyL & 7;

    const int rl0 = 16 * wid + (lane >> 2);
    const int cl0 = 2 * (lane & 3);

    float d_y[8][4];
    #pragma unroll
    for (int j = 0; j < 8; j++)
        #pragma unroll
        for (int v = 0; v < 4; v++) d_y[j][v] = 0.f;
    float lsum0 = 0.f, lsum1 = 0.f;

    for (int kt = 0; kt < nkt; kt++) {
        const int buf = (kt + 1) & 1;
        if (kt + 1 < nkt) {
            const uint32_t base = sb + (uint32_t)((kt & 1) * 65536);
            const size_t tof = (size_t)(kt + 1) * 128 * 64;
            #pragma unroll
            for (int i = 0; i < 4; i++) {
                const int idx = tid + 256 * i;
                const int r = idx >> 3, c = idx & 7;
                const uint32_t off = (uint32_t)(r * 128 + ((c ^ (r & 7)) << 4));
                const size_t so = tof + (size_t)r * 64 + c * 8;
                CP16(base + AKH + off, khp + so);
                CP16(base + AKL + off, klp + so);
                CP16(base + AVH + off, vhp + so);
                CP16(base + AVL + off, vlp + so);
            }
            CPCOMMIT();
            CPWAIT1();
        } else {
            CPWAIT0();
        }
        __syncthreads();

        const uint32_t base = sb + (uint32_t)(buf * 65536);

        float ds[16][4];
        #pragma unroll
        for (int j = 0; j < 16; j++)
            #pragma unroll
            for (int v = 0; v < 4; v++) ds[j][v] = 0.f;

        #pragma unroll
        for (int kk = 0; kk < 4; kk++) {
            #pragma unroll
            for (int j16 = 0; j16 < 8; j16++) {
                const uint32_t ka = base + AKH + (uint32_t)(j16 * 2048) + brow +
                                    (uint32_t)((((kk << 1) | bchk) ^ bsw) << 4);
                uint32_t khf[4], klf[4];
                ldm_x4(khf, ka);
                ldm_x4(klf, ka + 16384);
                uint32_t b0h[2] = {khf[0], khf[1]}, b1h[2] = {khf[2], khf[3]};
                uint32_t b0l[2] = {klf[0], klf[1]}, b1l[2] = {klf[2], klf[3]};
                mma_bf16(ds[2*j16],   q_h[kk], b0h);
                mma_bf16(ds[2*j16],   q_h[kk], b0l);
                mma_bf16(ds[2*j16],   q_l[kk], b0h);
                mma_bf16(ds[2*j16+1], q_h[kk], b1h);
                mma_bf16(ds[2*j16+1], q_h[kk], b1l);
                mma_bf16(ds[2*j16+1], q_l[kk], b1h);
            }
        }

        const bool diag = (kt == qt);
        const int ktbase = kt * 128;
        #pragma unroll
        for (int j = 0; j < 16; j++) {
            const int c = 8 * j + cl0;
            float e00 = __expf(ds[j][0]);
            float e01 = __expf(ds[j][1]);
            float e10 = __expf(ds[j][2]);
            float e11 = __expf(ds[j][3]);
            if (diag) {
                if (c     > rl0)     e00 = 0.f;
                if (c + 1 > rl0)     e01 = 0.f;
                if (c     > rl0 + 8) e10 = 0.f;
                if (c + 1 > rl0 + 8) e11 = 0.f;
            }
            ds[j][0] = e00; ds[j][1] = e01; ds[j][2] = e10; ds[j][3] = e11;
            *(float2*)(attp + (size_t)rl0 * Tn + ktbase + c)       = make_float2(e00, e01);
            *(float2*)(attp + (size_t)(rl0 + 8) * Tn + ktbase + c) = make_float2(e10, e11);
            lsum0 += e00 + e01;
            lsum1 += e10 + e11;
        }

        #pragma unroll
        for (int kap = 0; kap < 8; kap++) {
            uint32_t p_h[4], p_l[4];
            split2(ds[2*kap][0],   ds[2*kap][1],   p_h[0], p_l[0]);
            split2(ds[2*kap][2],   ds[2*kap][3],   p_h[1], p_l[1]);
            split2(ds[2*kap+1][0], ds[2*kap+1][1], p_h[2], p_l[2]);
            split2(ds[2*kap+1][2], ds[2*kap+1][3], p_h[3], p_l[3]);
            #pragma unroll
            for (int j16 = 0; j16 < 4; j16++) {
                const uint32_t va = base + AVH + (uint32_t)(kap * 2048) + vrow +
                                    (uint32_t)((((j16 << 1) | vchk) ^ vsw) << 4);
                uint32_t vhf[4], vlf[4];
                ldm_x4_t(vhf, va);
                ldm_x4_t(vlf, va + 16384);
                uint32_t v0h[2] = {vhf[0], vhf[1]}, v1h[2] = {vhf[2], vhf[3]};
                uint32_t v0l[2] = {vlf[0], vlf[1]}, v1l[2] = {vlf[2], vlf[3]};
                mma_bf16(d_y[2*j16],   p_h, v0h);
                mma_bf16(d_y[2*j16],   p_h, v0l);
                mma_bf16(d_y[2*j16],   p_l, v0h);
                mma_bf16(d_y[2*j16+1], p_h, v1h);
                mma_bf16(d_y[2*j16+1], p_h, v1l);
                mma_bf16(d_y[2*j16+1], p_l, v1h);
            }
        }
        __syncthreads();
    }

    // finalize: row sums, write y as bf16 hi/lo
    lsum0 += __shfl_xor_sync(0xffffffffu, lsum0, 1);
    lsum0 += __shfl_xor_sync(0xffffffffu, lsum0, 2);
    lsum1 += __shfl_xor_sync(0xffffffffu, lsum1, 1);
    lsum1 += __shfl_xor_sync(0xffffffffu, lsum1, 2);
    const float inv0 = 1.f / lsum0;
    const float inv1 = 1.f / lsum1;
    if ((lane & 3) == 0) {
        g_lsum[(size_t)bh * Tn + qbase + rl0]     = lsum0;
        g_lsum[(size_t)bh * Tn + qbase + rl0 + 8] = lsum1;
    }
    const int b = bh >> 4, hh = bh & 15;
    const size_t y0i = ((size_t)(b * Tn + qbase + rl0)) * Cn + hh * 64;
    const size_t y1i = y0i + (size_t)8 * Cn;
    #pragma unroll
    for (int j = 0; j < 8; j++) {
        uint32_t h, l;
        split2(d_y[j][0] * inv0, d_y[j][1] * inv0, h, l);
        *(uint32_t*)(g_yh + y0i + 8 * j + cl0) = h;
        *(uint32_t*)(g_yl + y0i + 8 * j + cl0) = l;
        split2(d_y[j][2] * inv1, d_y[j][3] * inv1, h, l);
        *(uint32_t*)(g_yh + y1i + 8 * j + cl0) = h;
        *(uint32_t*)(g_yl + y1i + 8 * j + cl0) = l;
    }
}

// ---------------------------------------------------------------------------
// Normalize att rows by 1/l (lower-triangle region only). Warp per row.
// ---------------------------------------------------------------------------
__global__ __launch_bounds__(256) void norm_att(float* __restrict__ att)
{
    const int wid = threadIdx.x >> 5, lane = threadIdx.x & 31;
    const size_t row = (size_t)blockIdx.x * 8 + wid;
    const int rs = (int)(row & (Tn - 1));
    const int width = ((rs >> 7) + 1) * 128;
    const float inv = 1.f / g_lsum[row];
    float* p = att + row * Tn;
    for (int c = lane * 4; c < width; c += 128) {
        float4 v = *(float4*)(p + c);
        v.x *= inv; v.y *= inv; v.z *= inv; v.w *= inv;
        *(float4*)(p + c) = v;
    }
}

// ---------------------------------------------------------------------------
extern "C" void kernel_launch(void* const* d_in, const int* in_sizes, int n_in,
                              void* d_out, int out_size)
{
    const float* x  = (const float*)d_in[0];
    const float* bq = (const float*)d_in[2];
    const float* bk = (const float*)d_in[4];
    const float* bv = (const float*)d_in[6];
    const float* Wq = (const float*)d_in[1];
    const float* Wk = (const float*)d_in[3];
    const float* Wv = (const float*)d_in[5];
    const float* Wp = (const float*)d_in[7];
    const float* bp = (const float*)d_in[8];

    float* y_out   = (float*)d_out;                       // [B,T,C]
    float* att_out = y_out + (size_t)BT * Cn;             // [B,H,T,T]

    cudaFuncSetAttribute(gemm_qkv_tc,  cudaFuncAttributeMaxDynamicSharedMemorySize, GEMM_SMEM);
    cudaFuncSetAttribute(gemm_proj_tc, cudaFuncAttributeMaxDynamicSharedMemorySize, GEMM_SMEM);
    cudaFuncSetAttribute(attn_mma,     cudaFuncAttributeMaxDynamicSharedMemorySize, ATT_SMEM);

    // pre-split x and weights to bf16 hi/lo
    conv_x<<<(BT * Cn / 4) / 256, 256>>>((const float4*)x);
    conv_w<<<dim3((Cn * Cn / 4) / 256, 4), 256>>>(Wq, Wk, Wv, Wp);

    // QKV projections -> bf16 hi/lo q,k,v (q pre-scaled by 1/8)
    gemm_qkv_tc<<<dim3(8, 64, 3), 256, GEMM_SMEM>>>(bq, bk, bv);

    // Fused MMA attention: unnormalized E -> att, row sums, y = E@V / l (bf16 out)
    attn_mma<<<dim3(NQT, Bn * Hn), 256, ATT_SMEM>>>(att_out);

    // Normalize att lower triangle by 1/l
    norm_att<<<(64 * Tn) / 8, 256>>>(att_out);

    // Output projection
    gemm_proj_tc<<<dim3(8, 64), 256, GEMM_SMEM>>>(bp, y_out);
}